// round 11
// baseline (speedup 1.0000x reference)
#include <cuda_runtime.h>
#include <cuda_bf16.h>
#include <math.h>

#define NC    128
#define LL    250
#define MM    32
#define NCOL  250000
#define TOT   32000000
#define PERB  8000000
#define PITCH 132

// Scratch
__device__ float g_buf0[32000000];  // u (packed) -> G (glu out, flat) -> u_inter
__device__ float g_buf1[32000000];  // yT -> Lf (lw out, flat)
__device__ float g_kern[NC * LL];
__device__ double g_stats[8];
__device__ float g_mu[4], g_inv[4];
// ow pre-converted to bf16 A3 = [Ah | Ah | Al], row-major 256 x 384 (u32-packed pairs)
__device__ unsigned g_owA[256 * 192];
// lw pre-converted to bf16 B3 = [Wh | Wl | Wh], per-col k-contiguous 128 x 384
__device__ unsigned g_lwB[128 * 192];

// ---------------------------------------------------------------------------
typedef unsigned long long u64;
__device__ __forceinline__ u64 dup2(float x) {
    u64 r; asm("mov.b64 %0,{%1,%1};" : "=l"(r) : "f"(x)); return r;
}
__device__ __forceinline__ u64 pk2(float x, float y) {
    u64 r; asm("mov.b64 %0,{%1,%2};" : "=l"(r) : "f"(x), "f"(y)); return r;
}
__device__ __forceinline__ void fma2(u64& a, u64 b, u64 c) {
    asm("fma.rn.f32x2 %0,%1,%2,%0;" : "+l"(a) : "l"(b), "l"(c));
}
__device__ __forceinline__ void un2(u64 v, float& x, float& y) {
    asm("mov.b64 {%0,%1},%2;" : "=f"(x), "=f"(y) : "l"(v));
}
__device__ __forceinline__ void mma16816(float& c0, float& c1, float& c2, float& c3,
                                         unsigned a0, unsigned a1, unsigned a2, unsigned a3,
                                         unsigned b0, unsigned b1) {
    asm volatile(
        "mma.sync.aligned.m16n8k16.row.col.f32.bf16.bf16.f32 "
        "{%0,%1,%2,%3}, {%4,%5,%6,%7}, {%8,%9}, {%0,%1,%2,%3};"
        : "+f"(c0), "+f"(c1), "+f"(c2), "+f"(c3)
        : "r"(a0), "r"(a1), "r"(a2), "r"(a3), "r"(b0), "r"(b1));
}
__device__ __forceinline__ unsigned pkbf(__nv_bfloat16 a, __nv_bfloat16 b) {
    unsigned r;
    asm("mov.b32 %0, {%1, %2};" : "=r"(r)
        : "h"(*(unsigned short*)&a), "h"(*(unsigned short*)&b));
    return r;
}
__device__ __forceinline__ unsigned smem_u32p(const void* p) {
    return (unsigned)__cvta_generic_to_shared(p);
}
#define CP_ASYNC16(dst_u32, gptr) \
    asm volatile("cp.async.cg.shared.global [%0], [%1], 16;" :: "r"(dst_u32), "l"(gptr))
#define CP_COMMIT() asm volatile("cp.async.commit_group;" ::: "memory")
#define CP_WAIT0()  asm volatile("cp.async.wait_group 0;" ::: "memory")

// ---------------------------------------------------------------------------
__global__ void pack_intra(const float* __restrict__ x) {
    __shared__ float tile[32][33];
    int bh = blockIdx.y;
    int b = bh >> 7, h = bh & 127;
    int tk = blockIdx.x & 7;
    int ts = blockIdx.x >> 3;
    int k = tk * 32 + threadIdx.y;
    int s = ts * 32 + threadIdx.x;
    if (k < 250 && s < 250)
        tile[threadIdx.y][threadIdx.x] = x[(((long)bh * 250 + k) * 250) + s];
    __syncthreads();
    int s2 = ts * 32 + threadIdx.y;
    int k2 = tk * 32 + threadIdx.x;
    if (s2 < 250 && k2 < 250)
        g_buf0[(((long)(b * 250 + s2) * 128 + h) * 250) + k2] = tile[threadIdx.x][threadIdx.y];
}

// ---------------------------------------------------------------------------
__global__ void kern_compute(const float* __restrict__ log_dt,
                             const float* __restrict__ logA_re,
                             const float* __restrict__ A_im,
                             const float* __restrict__ C_re,
                             const float* __restrict__ C_im) {
    __shared__ float sCr[MM], sCi[MM], sar[MM], sai[MM];
    int h = blockIdx.x;
    int t = threadIdx.x;
    if (t < MM) {
        float dt  = expf(log_dt[h]);
        float Are = -expf(logA_re[h * MM + t]);
        float Aim = A_im[h * MM + t];
        float ar = dt * Are, ai = dt * Aim;
        float ea = expf(ar);
        float sb, cb; sincosf(ai, &sb, &cb);
        float er = ea * cb - 1.f, ei = ea * sb;
        float den = Are * Are + Aim * Aim;
        float qr = (er * Are + ei * Aim) / den;
        float qi = (ei * Are - er * Aim) / den;
        float cr = C_re[h * MM + t], ci = C_im[h * MM + t];
        sCr[t] = cr * qr - ci * qi;
        sCi[t] = cr * qi + ci * qr;
        sar[t] = ar; sai[t] = ai;
    }
    __syncthreads();
    if (t < LL) {
        float fl = (float)t;
        float sum = 0.f;
        #pragma unroll
        for (int m = 0; m < MM; ++m) {
            float ea = expf(sar[m] * fl);
            float sb, cb; sincosf(sai[m] * fl, &sb, &cb);
            sum += ea * (sCr[m] * cb - sCi[m] * sb);
        }
        g_kern[h * LL + t] = 2.f * sum;
    }
}

// ---------------------------------------------------------------------------
// Conv as per-h Toeplitz GEMM + D*u + GELU (f32x2 CUDA cores).
__global__ void __launch_bounds__(256, 2)
conv_gemm(const float* __restrict__ D) {
    __shared__ float As[32 * PITCH];
    __shared__ float Bs[32 * PITCH];
    __shared__ float skp[512];
    int tid = threadIdx.x;
    int h = blockIdx.y;
    int rowblk = blockIdx.x >> 1, colblk = blockIdx.x & 1;
    int r0 = rowblk * 128;
    int t0 = colblk * 128;
    int nkt = colblk ? 8 : 4;

    skp[tid] = 0.f;
    skp[256 + tid] = (tid < 250) ? g_kern[h * 250 + tid] : 0.f;
    __syncthreads();

    int tx = tid & 15, ty = tid >> 4;
    u64 acc[8][4];
    #pragma unroll
    for (int i = 0; i < 8; ++i)
        #pragma unroll
        for (int j = 0; j < 4; ++j) acc[i][j] = 0ull;

    for (int kt = 0; kt < nkt; ++kt) {
        int m0 = kt * 32;
        {
            int c4 = (tid & 7) * 4;
            int rb = tid >> 3;
            #pragma unroll
            for (int p = 0; p < 4; ++p) {
                int r = rb + p * 32;
                int bb = r0 + r; if (bb > 999) bb = 999;
                const float* up = g_buf0 + ((long)bb * 128 + h) * 250 + m0 + c4;
                float2 v0 = (m0 + c4     < 250) ? *(const float2*)(up)     : make_float2(0.f, 0.f);
                float2 v1 = (m0 + c4 + 2 < 250) ? *(const float2*)(up + 2) : make_float2(0.f, 0.f);
                As[(c4 + 0) * PITCH + r] = v0.x; As[(c4 + 1) * PITCH + r] = v0.y;
                As[(c4 + 2) * PITCH + r] = v1.x; As[(c4 + 3) * PITCH + r] = v1.y;
            }
        }
        {
            int mm = tid >> 3;
            int ttb = (tid & 7) * 16;
            int base = 256 + t0 - m0 - mm + ttb;
            #pragma unroll
            for (int q = 0; q < 16; ++q)
                Bs[mm * PITCH + ttb + q] = skp[base + q];
        }
        __syncthreads();
        #pragma unroll
        for (int kk = 0; kk < 32; ++kk) {
            float4 a0 = *(const float4*)&As[kk * PITCH + ty * 8];
            float4 a1 = *(const float4*)&As[kk * PITCH + ty * 8 + 4];
            float4 b0 = *(const float4*)&Bs[kk * PITCH + tx * 8];
            float4 b1 = *(const float4*)&Bs[kk * PITCH + tx * 8 + 4];
            u64 ad[8] = {dup2(a0.x), dup2(a0.y), dup2(a0.z), dup2(a0.w),
                         dup2(a1.x), dup2(a1.y), dup2(a1.z), dup2(a1.w)};
            u64 bp4[4] = {pk2(b0.x, b0.y), pk2(b0.z, b0.w),
                          pk2(b1.x, b1.y), pk2(b1.z, b1.w)};
            #pragma unroll
            for (int i = 0; i < 8; ++i)
                #pragma unroll
                for (int j = 0; j < 4; ++j)
                    fma2(acc[i][j], ad[i], bp4[j]);
        }
        __syncthreads();
    }

    float dh = D[h];
    #pragma unroll
    for (int i = 0; i < 8; ++i) {
        int bb = r0 + ty * 8 + i;
        if (bb > 999) continue;
        float c[8];
        #pragma unroll
        for (int j = 0; j < 4; ++j) un2(acc[i][j], c[2 * j], c[2 * j + 1]);
        int tbase = t0 + tx * 8;
        const float* up = g_buf0 + ((long)bb * 128 + h) * 250 + tbase;
        float* yp = g_buf1 + (long)h * NCOL + (long)bb * 250 + tbase;
        #pragma unroll
        for (int j2 = 0; j2 < 4; ++j2) {
            int t = tbase + 2 * j2;
            if (t < 250) {
                float2 uv = *(const float2*)(up + 2 * j2);
                float y0 = c[2 * j2]     + dh * uv.x;
                float y1 = c[2 * j2 + 1] + dh * uv.y;
                float e0 = y0 + 0.044715f * y0 * y0 * y0;
                float e1 = y1 + 0.044715f * y1 * y1 * y1;
                float2 g;
                g.x = 0.5f * y0 * (1.f + tanhf(0.7978845608f * e0));
                g.y = 0.5f * y1 * (1.f + tanhf(0.7978845608f * e1));
                *(float2*)(yp + 2 * j2) = g;
            }
        }
    }
}

// ---------------------------------------------------------------------------
// Pre-convert ow -> A3 [Ah | Ah | Al]  and lw -> B3 [Wh | Wl | Wh]
__global__ void conv_ow_bf16(const float* __restrict__ ow) {
    int idx = blockIdx.x * 256 + threadIdx.x;
    int o = idx >> 6, kp = idx & 63;
    float v0 = ow[o * 128 + kp * 2];
    float v1 = ow[o * 128 + kp * 2 + 1];
    __nv_bfloat16 h0 = __float2bfloat16(v0);
    __nv_bfloat16 h1 = __float2bfloat16(v1);
    __nv_bfloat16 l0 = __float2bfloat16(v0 - __bfloat162float(h0));
    __nv_bfloat16 l1 = __float2bfloat16(v1 - __bfloat162float(h1));
    unsigned hp = pkbf(h0, h1), lp = pkbf(l0, l1);
    g_owA[o * 192 + kp]       = hp;
    g_owA[o * 192 + 64 + kp]  = hp;
    g_owA[o * 192 + 128 + kp] = lp;
}

__global__ void conv_lw_bf16(const float* __restrict__ W) {
    int idx = blockIdx.x * 256 + threadIdx.x;
    int c = idx >> 6, kp = idx & 63;
    float v0 = W[c * 128 + kp * 2];
    float v1 = W[c * 128 + kp * 2 + 1];
    __nv_bfloat16 h0 = __float2bfloat16(v0);
    __nv_bfloat16 h1 = __float2bfloat16(v1);
    __nv_bfloat16 l0 = __float2bfloat16(v0 - __bfloat162float(h0));
    __nv_bfloat16 l1 = __float2bfloat16(v1 - __bfloat162float(h1));
    unsigned hp = pkbf(h0, h1), lp = pkbf(l0, l1);
    g_lwB[c * 192 + kp]       = hp;   // pairs with Gh
    g_lwB[c * 192 + 64 + kp]  = lp;   // pairs with Gh
    g_lwB[c * 192 + 128 + kp] = hp;   // pairs with Gl
}

// ---------------------------------------------------------------------------
// mma.sync bf16 2-split fused ow GEMM + GLU, cp.async double-buffered A.
// Dyn smem: Bs16 @0 (50176) | Abuf 2x[256][20] u32 @50176 (40960)
//           | stash f32[128][66] @91136 (33792) | sbias @124928 (1024)
__global__ void __launch_bounds__(256)
gemm_ow_mma(const float* __restrict__ bias) {
    extern __shared__ char dsm[];
    __nv_bfloat16* Bs16 = (__nv_bfloat16*)dsm;          // [c][392]
    unsigned* Bsu = (unsigned*)dsm;                      // u32 view (stride 196)
    unsigned* Abuf = (unsigned*)(dsm + 50176);           // [2][256*20]
    float* stash = (float*)(dsm + 91136);                // [o2][66]
    float* sbias = (float*)(dsm + 124928);
    unsigned abase = smem_u32p(Abuf);

    int tid = threadIdx.x;
    int w = tid >> 5, lane = tid & 31;
    int g = lane >> 2, tg = lane & 3;
    int mw = w >> 1, nw = w & 1;
    long n0 = (long)blockIdx.x * 64;

    sbias[tid] = bias[tid];

    // prefetch A chunk 0
    {
        #pragma unroll
        for (int p = 0; p < 4; ++p) {
            int i = tid + p * 256;
            int o = i >> 2, q = i & 3;
            CP_ASYNC16(abase + (o * 20 + q * 4) * 4, g_owA + o * 192 + q * 4);
        }
        CP_COMMIT();
    }

    // Build B3 from yT
    for (int i = tid; i < 128 * 64; i += 256) {
        int hk = i >> 6, c = i & 63;
        long col = n0 + c; if (col >= NCOL) col = NCOL - 1;
        float v = g_buf1[(long)hk * NCOL + col];
        __nv_bfloat16 hi = __float2bfloat16(v);
        __nv_bfloat16 lo = __float2bfloat16(v - __bfloat162float(hi));
        __nv_bfloat16* bp = Bs16 + c * 392;
        bp[hk] = hi; bp[hk + 128] = lo; bp[hk + 256] = hi;
    }

    float acc[4][4][4];
    #pragma unroll
    for (int i = 0; i < 4; ++i)
        #pragma unroll
        for (int j = 0; j < 4; ++j)
            #pragma unroll
            for (int q = 0; q < 4; ++q) acc[i][j][q] = 0.f;

    for (int kc = 0; kc < 12; ++kc) {
        CP_WAIT0();
        __syncthreads();
        if (kc < 11) {
            int nbuf = (kc + 1) & 1;
            #pragma unroll
            for (int p = 0; p < 4; ++p) {
                int i = tid + p * 256;
                int o = i >> 2, q = i & 3;
                CP_ASYNC16(abase + (nbuf * 5120 + o * 20 + q * 4) * 4,
                           g_owA + o * 192 + (kc + 1) * 16 + q * 4);
            }
            CP_COMMIT();
        }
        unsigned* Ach = Abuf + (kc & 1) * 5120;
        #pragma unroll
        for (int s = 0; s < 2; ++s) {
            int ks = kc * 2 + s;
            unsigned bf0[4], bf1[4];
            #pragma unroll
            for (int j = 0; j < 4; ++j) {
                int c = nw * 32 + j * 8 + g;
                bf0[j] = Bsu[c * 196 + ks * 8 + tg];
                bf1[j] = Bsu[c * 196 + ks * 8 + tg + 4];
            }
            #pragma unroll
            for (int i = 0; i < 4; ++i) {
                int r0 = mw * 64 + i * 16 + g;
                int base0 = r0 * 20 + s * 8 + tg;
                int base1 = (r0 + 8) * 20 + s * 8 + tg;
                unsigned a0 = Ach[base0], a1 = Ach[base1];
                unsigned a2 = Ach[base0 + 4], a3 = Ach[base1 + 4];
                #pragma unroll
                for (int j = 0; j < 4; ++j)
                    mma16816(acc[i][j][0], acc[i][j][1], acc[i][j][2], acc[i][j][3],
                             a0, a1, a2, a3, bf0[j], bf1[j]);
            }
        }
    }
    __syncthreads();

    if (w >= 4) {
        #pragma unroll
        for (int i = 0; i < 4; ++i) {
            int m = mw * 64 + i * 16 + g;
            int o2a = m - 128, o2b = m - 120;
            float ba = sbias[128 + o2a], bb2 = sbias[128 + o2b];
            #pragma unroll
            for (int j = 0; j < 4; ++j) {
                int cl = nw * 32 + j * 8 + tg * 2;
                stash[o2a * 66 + cl]     = acc[i][j][0] + ba;
                stash[o2a * 66 + cl + 1] = acc[i][j][1] + ba;
                stash[o2b * 66 + cl]     = acc[i][j][2] + bb2;
                stash[o2b * 66 + cl + 1] = acc[i][j][3] + bb2;
            }
        }
    }
    __syncthreads();

    if (w < 4) {
        #pragma unroll
        for (int i = 0; i < 4; ++i) {
            int oa = mw * 64 + i * 16 + g;
            int ob = oa + 8;
            float ba = sbias[oa], bb2 = sbias[ob];
            #pragma unroll
            for (int j = 0; j < 4; ++j) {
                int cl = nw * 32 + j * 8 + tg * 2;
                long col = n0 + cl;
                if (col < NCOL) {
                    int bb = (int)(col / 250);
                    int l  = (int)(col - (long)bb * 250);
                    float z1a = acc[i][j][0] + ba;
                    float z1b = acc[i][j][1] + ba;
                    float z2a = stash[oa * 66 + cl];
                    float z2b = stash[oa * 66 + cl + 1];
                    float2 gv;
                    gv.x = z1a / (1.f + expf(-z2a));
                    gv.y = z1b / (1.f + expf(-z2b));
                    *(float2*)&g_buf0[((long)bb * 128 + oa) * 250 + l] = gv;
                    float z3a = acc[i][j][2] + bb2;
                    float z3b = acc[i][j][3] + bb2;
                    float z4a = stash[ob * 66 + cl];
                    float z4b = stash[ob * 66 + cl + 1];
                    float2 gw;
                    gw.x = z3a / (1.f + expf(-z4a));
                    gw.y = z3b / (1.f + expf(-z4b));
                    *(float2*)&g_buf0[((long)bb * 128 + ob) * 250 + l] = gw;
                }
            }
        }
    }
}

// ---------------------------------------------------------------------------
// mma.sync bf16 2-split lw GEMM + stats: G converted ONCE to smem Ahi/Alo,
// weight B streamed via cp.async double buffer.
// Dyn smem: Ahi [128][68] u32 @0 (34816) | Alo @34816 (34816)
//           | Bbuf 2x[128][20] u32 @69632 (20480) | sbias @90112 | red @90624
__global__ void __launch_bounds__(256)
gemm_lw_mma(const float* __restrict__ bias) {
    extern __shared__ char dsm[];
    unsigned* Ahi = (unsigned*)dsm;
    unsigned* Alo = (unsigned*)(dsm + 34816);
    unsigned* Bbuf = (unsigned*)(dsm + 69632);
    float* sbias = (float*)(dsm + 90112);
    float* red = (float*)(dsm + 90624);      // [8][4]
    unsigned bbase = smem_u32p(Bbuf);

    int tid = threadIdx.x;
    int w = tid >> 5, lane = tid & 31;
    int g = lane >> 2, tg = lane & 3;
    int mw = w >> 1, nw = w & 1;
    long r0 = (long)blockIdx.x * 128;

    if (tid < 128) sbias[tid] = bias[tid];

    // prefetch B chunk 0
    {
        #pragma unroll
        for (int p = 0; p < 2; ++p) {
            int i = tid + p * 256;
            int c = i >> 2, q = i & 3;
            CP_ASYNC16(bbase + (c * 20 + q * 4) * 4, g_lwB + c * 192 + q * 4);
        }
        CP_COMMIT();
    }

    // Convert G block once: Ahi/Alo [128 rows][64 u32]
    #pragma unroll
    for (int p = 0; p < 32; ++p) {
        int i = tid + p * 256;
        int r = i >> 6, kk = i & 63;
        long row = r0 + r; if (row >= NCOL) row = NCOL - 1;
        float2 v = *(const float2*)&g_buf0[row * 128 + kk * 2];
        __nv_bfloat16 h0 = __float2bfloat16(v.x);
        __nv_bfloat16 h1 = __float2bfloat16(v.y);
        __nv_bfloat16 l0 = __float2bfloat16(v.x - __bfloat162float(h0));
        __nv_bfloat16 l1 = __float2bfloat16(v.y - __bfloat162float(h1));
        Ahi[r * 68 + kk] = pkbf(h0, h1);
        Alo[r * 68 + kk] = pkbf(l0, l1);
    }

    float acc[2][8][4];
    #pragma unroll
    for (int i = 0; i < 2; ++i)
        #pragma unroll
        for (int j = 0; j < 8; ++j)
            #pragma unroll
            for (int q = 0; q < 4; ++q) acc[i][j][q] = 0.f;

    for (int kc = 0; kc < 12; ++kc) {
        CP_WAIT0();
        __syncthreads();
        if (kc < 11) {
            int nbuf = (kc + 1) & 1;
            #pragma unroll
            for (int p = 0; p < 2; ++p) {
                int i = tid + p * 256;
                int c = i >> 2, q = i & 3;
                CP_ASYNC16(bbase + (nbuf * 2560 + c * 20 + q * 4) * 4,
                           g_lwB + c * 192 + (kc + 1) * 16 + q * 4);
            }
            CP_COMMIT();
        }
        unsigned* Bch = Bbuf + (kc & 1) * 2560;
        #pragma unroll
        for (int s = 0; s < 2; ++s) {
            int ks = kc * 2 + s;
            const unsigned* Asrc = (ks < 16) ? Ahi : Alo;
            int grp = (ks < 16) ? (ks & 7) : (ks - 16);
            unsigned bf0[8], bf1[8];
            #pragma unroll
            for (int j = 0; j < 8; ++j) {
                int c = nw * 64 + j * 8 + g;
                bf0[j] = Bch[c * 20 + s * 8 + tg];
                bf1[j] = Bch[c * 20 + s * 8 + tg + 4];
            }
            #pragma unroll
            for (int i = 0; i < 2; ++i) {
                int rr = mw * 32 + i * 16 + g;
                int base0 = rr * 68 + grp * 8 + tg;
                int base1 = (rr + 8) * 68 + grp * 8 + tg;
                unsigned a0 = Asrc[base0], a1 = Asrc[base1];
                unsigned a2 = Asrc[base0 + 4], a3 = Asrc[base1 + 4];
                #pragma unroll
                for (int j = 0; j < 8; ++j)
                    mma16816(acc[i][j][0], acc[i][j][1], acc[i][j][2], acc[i][j][3],
                             a0, a1, a2, a3, bf0[j], bf1[j]);
            }
        }
    }
    __syncthreads();

    // Epilogue: bias, store, stats
    int b0idx = (int)(r0 / 62500);
    float s0 = 0.f, q0 = 0.f, s1 = 0.f, q1 = 0.f;
    #pragma unroll
    for (int i = 0; i < 2; ++i) {
        long ra = r0 + mw * 32 + i * 16 + g;
        long rb = ra + 8;
        #pragma unroll
        for (int j = 0; j < 8; ++j) {
            int c = nw * 64 + j * 8 + tg * 2;
            float bv0 = sbias[c], bv1 = sbias[c + 1];
            if (ra < NCOL) {
                float v0 = acc[i][j][0] + bv0;
                float v1 = acc[i][j][1] + bv1;
                *(float2*)&g_buf1[ra * 128 + c] = make_float2(v0, v1);
                float rs = v0 + v1, rq = v0 * v0 + v1 * v1;
                if ((int)(ra / 62500) == b0idx) { s0 += rs; q0 += rq; }
                else                            { s1 += rs; q1 += rq; }
            }
            if (rb < NCOL) {
                float v2 = acc[i][j][2] + bv0;
                float v3 = acc[i][j][3] + bv1;
                *(float2*)&g_buf1[rb * 128 + c] = make_float2(v2, v3);
                float rs = v2 + v3, rq = v2 * v2 + v3 * v3;
                if ((int)(rb / 62500) == b0idx) { s0 += rs; q0 += rq; }
                else                            { s1 += rs; q1 += rq; }
            }
        }
    }
    #pragma unroll
    for (int off = 16; off; off >>= 1) {
        s0 += __shfl_down_sync(0xffffffffu, s0, off);
        q0 += __shfl_down_sync(0xffffffffu, q0, off);
        s1 += __shfl_down_sync(0xffffffffu, s1, off);
        q1 += __shfl_down_sync(0xffffffffu, q1, off);
    }
    if (lane == 0) { red[w * 4 + 0] = s0; red[w * 4 + 1] = q0; red[w * 4 + 2] = s1; red[w * 4 + 3] = q1; }
    __syncthreads();
    if (tid == 0) {
        float ts0 = 0.f, tq0 = 0.f, ts1 = 0.f, tq1 = 0.f;
        #pragma unroll
        for (int j = 0; j < 8; ++j) {
            ts0 += red[j * 4 + 0]; tq0 += red[j * 4 + 1];
            ts1 += red[j * 4 + 2]; tq1 += red[j * 4 + 3];
        }
        atomicAdd(&g_stats[2 * b0idx],     (double)ts0);
        atomicAdd(&g_stats[2 * b0idx + 1], (double)tq0);
        if (b0idx < 3) {
            atomicAdd(&g_stats[2 * b0idx + 2], (double)ts1);
            atomicAdd(&g_stats[2 * b0idx + 3], (double)tq1);
        }
    }
}

// ---------------------------------------------------------------------------
__global__ void zero_stats() {
    if (threadIdx.x < 8) g_stats[threadIdx.x] = 0.0;
}

__global__ void finalize_stats() {
    int b = threadIdx.x;
    if (b < 4) {
        double mu  = g_stats[2 * b] / (double)PERB;
        double var = g_stats[2 * b + 1] / (double)PERB - mu * mu;
        g_mu[b]  = (float)mu;
        g_inv[b] = (float)(1.0 / sqrt(var + 1e-8));
    }
}

__global__ void trans_norm_intra(const float* __restrict__ gg, const float* __restrict__ gb,
                                 const float* __restrict__ x, float* __restrict__ out) {
    __shared__ float tile[32][33];
    int bn = blockIdx.y;
    int b = bn >> 7, n = bn & 127;
    int tk = blockIdx.x & 7, ts = blockIdx.x >> 3;
    int s = ts * 32 + threadIdx.y;
    int k = tk * 32 + threadIdx.x;
    if (s < 250 && k < 250)
        tile[threadIdx.y][threadIdx.x] =
            g_buf1[((long)(b * 250 + s)) * 32000 + n * 250 + k];
    __syncthreads();
    int k2 = tk * 32 + threadIdx.y;
    int s2 = ts * 32 + threadIdx.x;
    if (k2 < 250 && s2 < 250) {
        float mu = g_mu[b], inv = g_inv[b];
        long oi = (((long)(b * 128 + n)) * 250 + k2) * 250 + s2;
        float val = (tile[threadIdx.x][threadIdx.y] - mu) * inv * gg[n] + gb[n] + x[oi];
        out[oi] = val;
        g_buf0[(((long)(b * 250 + k2)) * 128 + n) * 250 + s2] = val;
    }
}

__global__ void norm_final(const float* __restrict__ gg, const float* __restrict__ gb,
                           float* __restrict__ out) {
    int i = blockIdx.x * 256 + threadIdx.x;
    int s = i % 250;
    int t = i / 250;
    int k = t % 250; t /= 250;
    int n = t & 127;
    int b = t >> 7;
    float mu = g_mu[b], inv = g_inv[b];
    float v = g_buf1[((long)(b * 250 + k)) * 32000 + n * 250 + s];
    out[i] = (v - mu) * inv * gg[n] + gb[n] + out[i];
}

// ---------------------------------------------------------------------------
extern "C" void kernel_launch(void* const* d_in, const int* in_sizes, int n_in,
                              void* d_out, int out_size) {
    const float* x = (const float*)d_in[0];
    const float* ip[12];
    const float* pp[12];
    for (int j = 0; j < 12; ++j) ip[j] = (const float*)d_in[1 + j];
    for (int j = 0; j < 12; ++j) pp[j] = (const float*)d_in[13 + j];
    float* out = (float*)d_out;

    const int EB = TOT / 256;
    const int SMEM_OW = 125952;
    const int SMEM_LW = 90752;
    cudaFuncSetAttribute(gemm_ow_mma, cudaFuncAttributeMaxDynamicSharedMemorySize, SMEM_OW);
    cudaFuncSetAttribute(gemm_lw_mma, cudaFuncAttributeMaxDynamicSharedMemorySize, SMEM_LW);
    const int GOW = (NCOL + 63) / 64;   // 3907

    // ---- intra path ----
    pack_intra<<<dim3(64, 512), dim3(32, 32)>>>(x);
    kern_compute<<<NC, 256>>>(ip[0], ip[1], ip[2], ip[3], ip[4]);
    conv_gemm<<<dim3(16, 128), 256>>>(ip[5]);
    conv_ow_bf16<<<64, 256>>>(ip[6]);
    conv_lw_bf16<<<32, 256>>>(ip[8]);
    gemm_ow_mma<<<GOW, 256, SMEM_OW>>>(ip[7]);
    zero_stats<<<1, 32>>>();
    gemm_lw_mma<<<1954, 256, SMEM_LW>>>(ip[9]);
    finalize_stats<<<1, 32>>>();
    trans_norm_intra<<<dim3(64, 512), dim3(32, 32)>>>(ip[10], ip[11], x, out);

    // ---- inter path ----
    kern_compute<<<NC, 256>>>(pp[0], pp[1], pp[2], pp[3], pp[4]);
    conv_gemm<<<dim3(16, 128), 256>>>(pp[5]);
    conv_ow_bf16<<<64, 256>>>(pp[6]);
    conv_lw_bf16<<<32, 256>>>(pp[8]);
    gemm_ow_mma<<<GOW, 256, SMEM_OW>>>(pp[7]);
    zero_stats<<<1, 32>>>();
    gemm_lw_mma<<<1954, 256, SMEM_LW>>>(pp[9]);
    finalize_stats<<<1, 32>>>();
    norm_final<<<EB, 256>>>(pp[10], pp[11], out);
}

// round 12
// speedup vs baseline: 1.1026x; 1.1026x over previous
#include <cuda_runtime.h>
#include <cuda_bf16.h>
#include <math.h>

#define NC    128
#define LL    250
#define MM    32
#define NCOL  250000
#define TOT   32000000
#define PERB  8000000
#define PITCH 132

// Scratch
__device__ float g_buf0[32000000];  // u (packed) -> G (glu out, flat) -> u_inter
__device__ float g_buf1[32000000];  // yT -> Lf (lw out, flat)
__device__ float g_kern[NC * LL];
__device__ double g_stats[8];
__device__ float g_mu[4], g_inv[4];
__device__ unsigned g_owA[256 * 192];   // ow bf16 [Ah|Ah|Al] 256x384
__device__ unsigned g_lwB[128 * 192];   // lw bf16 [Wh|Wl|Wh] 128x384

// ---------------------------------------------------------------------------
typedef unsigned long long u64;
__device__ __forceinline__ u64 dup2(float x) {
    u64 r; asm("mov.b64 %0,{%1,%1};" : "=l"(r) : "f"(x)); return r;
}
__device__ __forceinline__ u64 pk2(float x, float y) {
    u64 r; asm("mov.b64 %0,{%1,%2};" : "=l"(r) : "f"(x), "f"(y)); return r;
}
__device__ __forceinline__ void fma2(u64& a, u64 b, u64 c) {
    asm("fma.rn.f32x2 %0,%1,%2,%0;" : "+l"(a) : "l"(b), "l"(c));
}
__device__ __forceinline__ void un2(u64 v, float& x, float& y) {
    asm("mov.b64 {%0,%1},%2;" : "=f"(x), "=f"(y) : "l"(v));
}
__device__ __forceinline__ void mma16816(float& c0, float& c1, float& c2, float& c3,
                                         unsigned a0, unsigned a1, unsigned a2, unsigned a3,
                                         unsigned b0, unsigned b1) {
    asm volatile(
        "mma.sync.aligned.m16n8k16.row.col.f32.bf16.bf16.f32 "
        "{%0,%1,%2,%3}, {%4,%5,%6,%7}, {%8,%9}, {%0,%1,%2,%3};"
        : "+f"(c0), "+f"(c1), "+f"(c2), "+f"(c3)
        : "r"(a0), "r"(a1), "r"(a2), "r"(a3), "r"(b0), "r"(b1));
}
__device__ __forceinline__ void ldm4(unsigned& r0, unsigned& r1, unsigned& r2, unsigned& r3,
                                     unsigned a) {
    asm volatile("ldmatrix.sync.aligned.m8n8.x4.shared.b16 {%0,%1,%2,%3}, [%4];"
        : "=r"(r0), "=r"(r1), "=r"(r2), "=r"(r3) : "r"(a));
}
__device__ __forceinline__ unsigned pkbf(__nv_bfloat16 a, __nv_bfloat16 b) {
    unsigned r;
    asm("mov.b32 %0, {%1, %2};" : "=r"(r)
        : "h"(*(unsigned short*)&a), "h"(*(unsigned short*)&b));
    return r;
}
__device__ __forceinline__ unsigned smem_u32p(const void* p) {
    return (unsigned)__cvta_generic_to_shared(p);
}

// ---------------------------------------------------------------------------
__global__ void pack_intra(const float* __restrict__ x) {
    __shared__ float tile[32][33];
    int bh = blockIdx.y;
    int b = bh >> 7, h = bh & 127;
    int tk = blockIdx.x & 7;
    int ts = blockIdx.x >> 3;
    int k = tk * 32 + threadIdx.y;
    int s = ts * 32 + threadIdx.x;
    if (k < 250 && s < 250)
        tile[threadIdx.y][threadIdx.x] = x[(((long)bh * 250 + k) * 250) + s];
    __syncthreads();
    int s2 = ts * 32 + threadIdx.y;
    int k2 = tk * 32 + threadIdx.x;
    if (s2 < 250 && k2 < 250)
        g_buf0[(((long)(b * 250 + s2) * 128 + h) * 250) + k2] = tile[threadIdx.x][threadIdx.y];
}

// ---------------------------------------------------------------------------
__global__ void kern_compute(const float* __restrict__ log_dt,
                             const float* __restrict__ logA_re,
                             const float* __restrict__ A_im,
                             const float* __restrict__ C_re,
                             const float* __restrict__ C_im) {
    __shared__ float sCr[MM], sCi[MM], sar[MM], sai[MM];
    int h = blockIdx.x;
    int t = threadIdx.x;
    if (t < MM) {
        float dt  = expf(log_dt[h]);
        float Are = -expf(logA_re[h * MM + t]);
        float Aim = A_im[h * MM + t];
        float ar = dt * Are, ai = dt * Aim;
        float ea = expf(ar);
        float sb, cb; sincosf(ai, &sb, &cb);
        float er = ea * cb - 1.f, ei = ea * sb;
        float den = Are * Are + Aim * Aim;
        float qr = (er * Are + ei * Aim) / den;
        float qi = (ei * Are - er * Aim) / den;
        float cr = C_re[h * MM + t], ci = C_im[h * MM + t];
        sCr[t] = cr * qr - ci * qi;
        sCi[t] = cr * qi + ci * qr;
        sar[t] = ar; sai[t] = ai;
    }
    __syncthreads();
    if (t < LL) {
        float fl = (float)t;
        float sum = 0.f;
        #pragma unroll
        for (int m = 0; m < MM; ++m) {
            float ea = expf(sar[m] * fl);
            float sb, cb; sincosf(sai[m] * fl, &sb, &cb);
            sum += ea * (sCr[m] * cb - sCi[m] * sb);
        }
        g_kern[h * LL + t] = 2.f * sum;
    }
}

// ---------------------------------------------------------------------------
// Conv as per-h Toeplitz GEMM + D*u + GELU (f32x2 CUDA cores).
__global__ void __launch_bounds__(256, 2)
conv_gemm(const float* __restrict__ D) {
    __shared__ float As[32 * PITCH];
    __shared__ float Bs[32 * PITCH];
    __shared__ float skp[512];
    int tid = threadIdx.x;
    int h = blockIdx.y;
    int rowblk = blockIdx.x >> 1, colblk = blockIdx.x & 1;
    int r0 = rowblk * 128;
    int t0 = colblk * 128;
    int nkt = colblk ? 8 : 4;

    skp[tid] = 0.f;
    skp[256 + tid] = (tid < 250) ? g_kern[h * 250 + tid] : 0.f;
    __syncthreads();

    int tx = tid & 15, ty = tid >> 4;
    u64 acc[8][4];
    #pragma unroll
    for (int i = 0; i < 8; ++i)
        #pragma unroll
        for (int j = 0; j < 4; ++j) acc[i][j] = 0ull;

    for (int kt = 0; kt < nkt; ++kt) {
        int m0 = kt * 32;
        {
            int c4 = (tid & 7) * 4;
            int rb = tid >> 3;
            #pragma unroll
            for (int p = 0; p < 4; ++p) {
                int r = rb + p * 32;
                int bb = r0 + r; if (bb > 999) bb = 999;
                const float* up = g_buf0 + ((long)bb * 128 + h) * 250 + m0 + c4;
                float2 v0 = (m0 + c4     < 250) ? *(const float2*)(up)     : make_float2(0.f, 0.f);
                float2 v1 = (m0 + c4 + 2 < 250) ? *(const float2*)(up + 2) : make_float2(0.f, 0.f);
                As[(c4 + 0) * PITCH + r] = v0.x; As[(c4 + 1) * PITCH + r] = v0.y;
                As[(c4 + 2) * PITCH + r] = v1.x; As[(c4 + 3) * PITCH + r] = v1.y;
            }
        }
        {
            int mm = tid >> 3;
            int ttb = (tid & 7) * 16;
            int base = 256 + t0 - m0 - mm + ttb;
            #pragma unroll
            for (int q = 0; q < 16; ++q)
                Bs[mm * PITCH + ttb + q] = skp[base + q];
        }
        __syncthreads();
        #pragma unroll
        for (int kk = 0; kk < 32; ++kk) {
            float4 a0 = *(const float4*)&As[kk * PITCH + ty * 8];
            float4 a1 = *(const float4*)&As[kk * PITCH + ty * 8 + 4];
            float4 b0 = *(const float4*)&Bs[kk * PITCH + tx * 8];
            float4 b1 = *(const float4*)&Bs[kk * PITCH + tx * 8 + 4];
            u64 ad[8] = {dup2(a0.x), dup2(a0.y), dup2(a0.z), dup2(a0.w),
                         dup2(a1.x), dup2(a1.y), dup2(a1.z), dup2(a1.w)};
            u64 bp4[4] = {pk2(b0.x, b0.y), pk2(b0.z, b0.w),
                          pk2(b1.x, b1.y), pk2(b1.z, b1.w)};
            #pragma unroll
            for (int i = 0; i < 8; ++i)
                #pragma unroll
                for (int j = 0; j < 4; ++j)
                    fma2(acc[i][j], ad[i], bp4[j]);
        }
        __syncthreads();
    }

    float dh = D[h];
    #pragma unroll
    for (int i = 0; i < 8; ++i) {
        int bb = r0 + ty * 8 + i;
        if (bb > 999) continue;
        float c[8];
        #pragma unroll
        for (int j = 0; j < 4; ++j) un2(acc[i][j], c[2 * j], c[2 * j + 1]);
        int tbase = t0 + tx * 8;
        const float* up = g_buf0 + ((long)bb * 128 + h) * 250 + tbase;
        float* yp = g_buf1 + (long)h * NCOL + (long)bb * 250 + tbase;
        #pragma unroll
        for (int j2 = 0; j2 < 4; ++j2) {
            int t = tbase + 2 * j2;
            if (t < 250) {
                float2 uv = *(const float2*)(up + 2 * j2);
                float y0 = c[2 * j2]     + dh * uv.x;
                float y1 = c[2 * j2 + 1] + dh * uv.y;
                float e0 = y0 + 0.044715f * y0 * y0 * y0;
                float e1 = y1 + 0.044715f * y1 * y1 * y1;
                float2 g;
                g.x = 0.5f * y0 * (1.f + tanhf(0.7978845608f * e0));
                g.y = 0.5f * y1 * (1.f + tanhf(0.7978845608f * e1));
                *(float2*)(yp + 2 * j2) = g;
            }
        }
    }
}

// ---------------------------------------------------------------------------
__global__ void conv_ow_bf16(const float* __restrict__ ow) {
    int idx = blockIdx.x * 256 + threadIdx.x;
    int o = idx >> 6, kp = idx & 63;
    float v0 = ow[o * 128 + kp * 2];
    float v1 = ow[o * 128 + kp * 2 + 1];
    __nv_bfloat16 h0 = __float2bfloat16(v0);
    __nv_bfloat16 h1 = __float2bfloat16(v1);
    __nv_bfloat16 l0 = __float2bfloat16(v0 - __bfloat162float(h0));
    __nv_bfloat16 l1 = __float2bfloat16(v1 - __bfloat162float(h1));
    unsigned hp = pkbf(h0, h1), lp = pkbf(l0, l1);
    g_owA[o * 192 + kp]       = hp;
    g_owA[o * 192 + 64 + kp]  = hp;
    g_owA[o * 192 + 128 + kp] = lp;
}

__global__ void conv_lw_bf16(const float* __restrict__ W) {
    int idx = blockIdx.x * 256 + threadIdx.x;
    int c = idx >> 6, kp = idx & 63;
    float v0 = W[c * 128 + kp * 2];
    float v1 = W[c * 128 + kp * 2 + 1];
    __nv_bfloat16 h0 = __float2bfloat16(v0);
    __nv_bfloat16 h1 = __float2bfloat16(v1);
    __nv_bfloat16 l0 = __float2bfloat16(v0 - __bfloat162float(h0));
    __nv_bfloat16 l1 = __float2bfloat16(v1 - __bfloat162float(h1));
    unsigned hp = pkbf(h0, h1), lp = pkbf(l0, l1);
    g_lwB[c * 192 + kp]       = hp;
    g_lwB[c * 192 + 64 + kp]  = lp;
    g_lwB[c * 192 + 128 + kp] = hp;
}

// ---------------------------------------------------------------------------
// mma.sync bf16 2-split fused ow GEMM + GLU, ldmatrix fragments.
// Dyn smem: Bs16 [64][392] bf16 @0 (50176) | Ach [256][20] u32 @50176 (20480)
//           | stash f32[128][66] @70656 (33792) | sbias @104448 (1024)
__global__ void __launch_bounds__(256)
gemm_ow_mma(const float* __restrict__ bias) {
    extern __shared__ char dsm[];
    __nv_bfloat16* Bs16 = (__nv_bfloat16*)dsm;          // [c][392]
    unsigned* Ach = (unsigned*)(dsm + 50176);            // [o][20]
    float* stash = (float*)(dsm + 70656);                // [o2][66]
    float* sbias = (float*)(dsm + 104448);

    int tid = threadIdx.x;
    int w = tid >> 5, lane = tid & 31;
    int g = lane >> 2, tg = lane & 3;
    int mw = w >> 1, nw = w & 1;
    long n0 = (long)blockIdx.x * 64;

    sbias[tid] = bias[tid];

    // Build B3 from yT
    for (int i = tid; i < 128 * 64; i += 256) {
        int hk = i >> 6, c = i & 63;
        long col = n0 + c; if (col >= NCOL) col = NCOL - 1;
        float v = g_buf1[(long)hk * NCOL + col];
        __nv_bfloat16 hi = __float2bfloat16(v);
        __nv_bfloat16 lo = __float2bfloat16(v - __bfloat162float(hi));
        __nv_bfloat16* bp = Bs16 + c * 392;
        bp[hk] = hi; bp[hk + 128] = lo; bp[hk + 256] = hi;
    }

    // ldmatrix per-lane base addresses
    // A (rows stride 20 u32 = 80B): rows sel (lane>>3)&1, k sel lane>>4
    unsigned aAddr = smem_u32p(Ach)
        + (((lane & 7) + ((lane >> 3) & 1) * 8 + mw * 64) * 20 + (lane >> 4) * 4) * 4;
    // B (rows stride 196 u32 = 784B): rows sel lane>>4, k sel (lane>>3)&1
    unsigned bAddr = smem_u32p(Bs16)
        + (((lane & 7) + (lane >> 4) * 8 + nw * 32) * 196 + ((lane >> 3) & 1) * 4) * 4;

    float acc[4][4][4];
    #pragma unroll
    for (int i = 0; i < 4; ++i)
        #pragma unroll
        for (int j = 0; j < 4; ++j)
            #pragma unroll
            for (int q = 0; q < 4; ++q) acc[i][j][q] = 0.f;

    for (int kc = 0; kc < 12; ++kc) {
        __syncthreads();
        // Load A chunk: 256 rows x 16 u32
        #pragma unroll
        for (int p = 0; p < 4; ++p) {
            int i = tid + p * 256;
            int o = i >> 2, q = i & 3;
            uint4 v = *(const uint4*)(g_owA + o * 192 + kc * 16 + q * 4);
            *(uint4*)&Ach[o * 20 + q * 4] = v;
        }
        __syncthreads();
        #pragma unroll
        for (int s = 0; s < 2; ++s) {
            int ks = kc * 2 + s;
            unsigned bf0[4], bf1[4];
            #pragma unroll
            for (int jp = 0; jp < 2; ++jp)
                ldm4(bf0[2 * jp], bf1[2 * jp], bf0[2 * jp + 1], bf1[2 * jp + 1],
                     bAddr + jp * 16 * 784 + ks * 32);
            #pragma unroll
            for (int i = 0; i < 4; ++i) {
                unsigned a0, a1, a2, a3;
                ldm4(a0, a1, a2, a3, aAddr + i * 1280 + s * 32);
                #pragma unroll
                for (int j = 0; j < 4; ++j)
                    mma16816(acc[i][j][0], acc[i][j][1], acc[i][j][2], acc[i][j][3],
                             a0, a1, a2, a3, bf0[j], bf1[j]);
            }
        }
    }
    __syncthreads();

    if (w >= 4) {
        #pragma unroll
        for (int i = 0; i < 4; ++i) {
            int m = mw * 64 + i * 16 + g;
            int o2a = m - 128, o2b = m - 120;
            float ba = sbias[128 + o2a], bb2 = sbias[128 + o2b];
            #pragma unroll
            for (int j = 0; j < 4; ++j) {
                int cl = nw * 32 + j * 8 + tg * 2;
                stash[o2a * 66 + cl]     = acc[i][j][0] + ba;
                stash[o2a * 66 + cl + 1] = acc[i][j][1] + ba;
                stash[o2b * 66 + cl]     = acc[i][j][2] + bb2;
                stash[o2b * 66 + cl + 1] = acc[i][j][3] + bb2;
            }
        }
    }
    __syncthreads();

    if (w < 4) {
        #pragma unroll
        for (int i = 0; i < 4; ++i) {
            int oa = mw * 64 + i * 16 + g;
            int ob = oa + 8;
            float ba = sbias[oa], bb2 = sbias[ob];
            #pragma unroll
            for (int j = 0; j < 4; ++j) {
                int cl = nw * 32 + j * 8 + tg * 2;
                long col = n0 + cl;
                if (col < NCOL) {
                    int bb = (int)(col / 250);
                    int l  = (int)(col - (long)bb * 250);
                    float z1a = acc[i][j][0] + ba;
                    float z1b = acc[i][j][1] + ba;
                    float z2a = stash[oa * 66 + cl];
                    float z2b = stash[oa * 66 + cl + 1];
                    float2 gv;
                    gv.x = z1a / (1.f + expf(-z2a));
                    gv.y = z1b / (1.f + expf(-z2b));
                    *(float2*)&g_buf0[((long)bb * 128 + oa) * 250 + l] = gv;
                    float z3a = acc[i][j][2] + bb2;
                    float z3b = acc[i][j][3] + bb2;
                    float z4a = stash[ob * 66 + cl];
                    float z4b = stash[ob * 66 + cl + 1];
                    float2 gw;
                    gw.x = z3a / (1.f + expf(-z4a));
                    gw.y = z3b / (1.f + expf(-z4b));
                    *(float2*)&g_buf0[((long)bb * 128 + ob) * 250 + l] = gw;
                }
            }
        }
    }
}

// ---------------------------------------------------------------------------
// mma.sync bf16 2-split lw GEMM + stats, ldmatrix fragments, G converted once.
// Dyn smem: Ahi [128][68] u32 @0 (34816) | Alo @34816 (34816)
//           | Bch [128][20] u32 @69632 (10240) | sbias @79872 (512) | red @80384 (128)
__global__ void __launch_bounds__(256)
gemm_lw_mma(const float* __restrict__ bias) {
    extern __shared__ char dsm[];
    unsigned* Ahi = (unsigned*)dsm;
    unsigned* Alo = (unsigned*)(dsm + 34816);
    unsigned* Bch = (unsigned*)(dsm + 69632);
    float* sbias = (float*)(dsm + 79872);
    float* red = (float*)(dsm + 80384);      // [8][4]

    int tid = threadIdx.x;
    int w = tid >> 5, lane = tid & 31;
    int g = lane >> 2, tg = lane & 3;
    int mw = w >> 1, nw = w & 1;
    long r0 = (long)blockIdx.x * 128;

    if (tid < 128) sbias[tid] = bias[tid];

    // Convert G block once: Ahi/Alo [128 rows][64 u32]
    #pragma unroll
    for (int p = 0; p < 32; ++p) {
        int i = tid + p * 256;
        int r = i >> 6, kk = i & 63;
        long row = r0 + r; if (row >= NCOL) row = NCOL - 1;
        float2 v = *(const float2*)&g_buf0[row * 128 + kk * 2];
        __nv_bfloat16 h0 = __float2bfloat16(v.x);
        __nv_bfloat16 h1 = __float2bfloat16(v.y);
        __nv_bfloat16 l0 = __float2bfloat16(v.x - __bfloat162float(h0));
        __nv_bfloat16 l1 = __float2bfloat16(v.y - __bfloat162float(h1));
        Ahi[r * 68 + kk] = pkbf(h0, h1);
        Alo[r * 68 + kk] = pkbf(l0, l1);
    }

    // ldmatrix per-lane base addresses
    unsigned aAddr = smem_u32p(Ahi)
        + (((lane & 7) + ((lane >> 3) & 1) * 8 + mw * 32) * 68 + (lane >> 4) * 4) * 4;
    unsigned bAddr = smem_u32p(Bch)
        + (((lane & 7) + (lane >> 4) * 8 + nw * 64) * 20 + ((lane >> 3) & 1) * 4) * 4;

    float acc[2][8][4];
    #pragma unroll
    for (int i = 0; i < 2; ++i)
        #pragma unroll
        for (int j = 0; j < 8; ++j)
            #pragma unroll
            for (int q = 0; q < 4; ++q) acc[i][j][q] = 0.f;

    for (int kc = 0; kc < 12; ++kc) {
        __syncthreads();
        // B chunk: 128 c x 16 u32
        #pragma unroll
        for (int p = 0; p < 2; ++p) {
            int i = tid + p * 256;
            int c = i >> 2, q = i & 3;
            uint4 v = *(const uint4*)(g_lwB + c * 192 + kc * 16 + q * 4);
            *(uint4*)&Bch[c * 20 + q * 4] = v;
        }
        __syncthreads();
        #pragma unroll
        for (int s = 0; s < 2; ++s) {
            int ks = kc * 2 + s;
            // A source offset: Ahi for ks<16 (data repeats every 8), Alo after
            unsigned aoff = (ks < 16) ? ((unsigned)(ks & 7) * 32)
                                      : (34816u + (unsigned)(ks - 16) * 32);
            unsigned bf0[8], bf1[8];
            #pragma unroll
            for (int jp = 0; jp < 4; ++jp)
                ldm4(bf0[2 * jp], bf1[2 * jp], bf0[2 * jp + 1], bf1[2 * jp + 1],
                     bAddr + jp * 16 * 80 + s * 32);
            #pragma unroll
            for (int i = 0; i < 2; ++i) {
                unsigned a0, a1, a2, a3;
                ldm4(a0, a1, a2, a3, aAddr + aoff + i * 16 * 272);
                #pragma unroll
                for (int j = 0; j < 8; ++j)
                    mma16816(acc[i][j][0], acc[i][j][1], acc[i][j][2], acc[i][j][3],
                             a0, a1, a2, a3, bf0[j], bf1[j]);
            }
        }
    }
    __syncthreads();

    // Epilogue: bias, store, stats
    int b0idx = (int)(r0 / 62500);
    float s0 = 0.f, q0 = 0.f, s1 = 0.f, q1 = 0.f;
    #pragma unroll
    for (int i = 0; i < 2; ++i) {
        long ra = r0 + mw * 32 + i * 16 + g;
        long rb = ra + 8;
        #pragma unroll
        for (int j = 0; j < 8; ++j) {
            int c = nw * 64 + j * 8 + tg * 2;
            float bv0 = sbias[c], bv1 = sbias[c + 1];
            if (ra < NCOL) {
                float v0 = acc[i][j][0] + bv0;
                float v1 = acc[i][j][1] + bv1;
                *(float2*)&g_buf1[ra * 128 + c] = make_float2(v0, v1);
                float rs = v0 + v1, rq = v0 * v0 + v1 * v1;
                if ((int)(ra / 62500) == b0idx) { s0 += rs; q0 += rq; }
                else                            { s1 += rs; q1 += rq; }
            }
            if (rb < NCOL) {
                float v2 = acc[i][j][2] + bv0;
                float v3 = acc[i][j][3] + bv1;
                *(float2*)&g_buf1[rb * 128 + c] = make_float2(v2, v3);
                float rs = v2 + v3, rq = v2 * v2 + v3 * v3;
                if ((int)(rb / 62500) == b0idx) { s0 += rs; q0 += rq; }
                else                            { s1 += rs; q1 += rq; }
            }
        }
    }
    #pragma unroll
    for (int off = 16; off; off >>= 1) {
        s0 += __shfl_down_sync(0xffffffffu, s0, off);
        q0 += __shfl_down_sync(0xffffffffu, q0, off);
        s1 += __shfl_down_sync(0xffffffffu, s1, off);
        q1 += __shfl_down_sync(0xffffffffu, q1, off);
    }
    if (lane == 0) { red[w * 4 + 0] = s0; red[w * 4 + 1] = q0; red[w * 4 + 2] = s1; red[w * 4 + 3] = q1; }
    __syncthreads();
    if (tid == 0) {
        float ts0 = 0.f, tq0 = 0.f, ts1 = 0.f, tq1 = 0.f;
        #pragma unroll
        for (int j = 0; j < 8; ++j) {
            ts0 += red[j * 4 + 0]; tq0 += red[j * 4 + 1];
            ts1 += red[j * 4 + 2]; tq1 += red[j * 4 + 3];
        }
        atomicAdd(&g_stats[2 * b0idx],     (double)ts0);
        atomicAdd(&g_stats[2 * b0idx + 1], (double)tq0);
        if (b0idx < 3) {
            atomicAdd(&g_stats[2 * b0idx + 2], (double)ts1);
            atomicAdd(&g_stats[2 * b0idx + 3], (double)tq1);
        }
    }
}

// ---------------------------------------------------------------------------
__global__ void zero_stats() {
    if (threadIdx.x < 8) g_stats[threadIdx.x] = 0.0;
}

__global__ void finalize_stats() {
    int b = threadIdx.x;
    if (b < 4) {
        double mu  = g_stats[2 * b] / (double)PERB;
        double var = g_stats[2 * b + 1] / (double)PERB - mu * mu;
        g_mu[b]  = (float)mu;
        g_inv[b] = (float)(1.0 / sqrt(var + 1e-8));
    }
}

__global__ void trans_norm_intra(const float* __restrict__ gg, const float* __restrict__ gb,
                                 const float* __restrict__ x, float* __restrict__ out) {
    __shared__ float tile[32][33];
    int bn = blockIdx.y;
    int b = bn >> 7, n = bn & 127;
    int tk = blockIdx.x & 7, ts = blockIdx.x >> 3;
    int s = ts * 32 + threadIdx.y;
    int k = tk * 32 + threadIdx.x;
    if (s < 250 && k < 250)
        tile[threadIdx.y][threadIdx.x] =
            g_buf1[((long)(b * 250 + s)) * 32000 + n * 250 + k];
    __syncthreads();
    int k2 = tk * 32 + threadIdx.y;
    int s2 = ts * 32 + threadIdx.x;
    if (k2 < 250 && s2 < 250) {
        float mu = g_mu[b], inv = g_inv[b];
        long oi = (((long)(b * 128 + n)) * 250 + k2) * 250 + s2;
        float val = (tile[threadIdx.x][threadIdx.y] - mu) * inv * gg[n] + gb[n] + x[oi];
        out[oi] = val;
        g_buf0[(((long)(b * 250 + k2)) * 128 + n) * 250 + s2] = val;
    }
}

__global__ void norm_final(const float* __restrict__ gg, const float* __restrict__ gb,
                           float* __restrict__ out) {
    int i = blockIdx.x * 256 + threadIdx.x;
    int s = i % 250;
    int t = i / 250;
    int k = t % 250; t /= 250;
    int n = t & 127;
    int b = t >> 7;
    float mu = g_mu[b], inv = g_inv[b];
    float v = g_buf1[((long)(b * 250 + k)) * 32000 + n * 250 + s];
    out[i] = (v - mu) * inv * gg[n] + gb[n] + out[i];
}

// ---------------------------------------------------------------------------
extern "C" void kernel_launch(void* const* d_in, const int* in_sizes, int n_in,
                              void* d_out, int out_size) {
    const float* x = (const float*)d_in[0];
    const float* ip[12];
    const float* pp[12];
    for (int j = 0; j < 12; ++j) ip[j] = (const float*)d_in[1 + j];
    for (int j = 0; j < 12; ++j) pp[j] = (const float*)d_in[13 + j];
    float* out = (float*)d_out;

    const int EB = TOT / 256;
    const int SMEM_OW = 105472;
    const int SMEM_LW = 80512;
    cudaFuncSetAttribute(gemm_ow_mma, cudaFuncAttributeMaxDynamicSharedMemorySize, SMEM_OW);
    cudaFuncSetAttribute(gemm_lw_mma, cudaFuncAttributeMaxDynamicSharedMemorySize, SMEM_LW);
    const int GOW = (NCOL + 63) / 64;   // 3907

    // ---- intra path ----
    pack_intra<<<dim3(64, 512), dim3(32, 32)>>>(x);
    kern_compute<<<NC, 256>>>(ip[0], ip[1], ip[2], ip[3], ip[4]);
    conv_gemm<<<dim3(16, 128), 256>>>(ip[5]);
    conv_ow_bf16<<<64, 256>>>(ip[6]);
    conv_lw_bf16<<<32, 256>>>(ip[8]);
    gemm_ow_mma<<<GOW, 256, SMEM_OW>>>(ip[7]);
    zero_stats<<<1, 32>>>();
    gemm_lw_mma<<<1954, 256, SMEM_LW>>>(ip[9]);
    finalize_stats<<<1, 32>>>();
    trans_norm_intra<<<dim3(64, 512), dim3(32, 32)>>>(ip[10], ip[11], x, out);

    // ---- inter path ----
    kern_compute<<<NC, 256>>>(pp[0], pp[1], pp[2], pp[3], pp[4]);
    conv_gemm<<<dim3(16, 128), 256>>>(pp[5]);
    conv_ow_bf16<<<64, 256>>>(pp[6]);
    conv_lw_bf16<<<32, 256>>>(pp[8]);
    gemm_ow_mma<<<GOW, 256, SMEM_OW>>>(pp[7]);
    zero_stats<<<1, 32>>>();
    gemm_lw_mma<<<1954, 256, SMEM_LW>>>(pp[9]);
    finalize_stats<<<1, 32>>>();
    norm_final<<<EB, 256>>>(pp[10], pp[11], out);
}

// round 13
// speedup vs baseline: 1.1371x; 1.0312x over previous
#include <cuda_runtime.h>
#include <cuda_bf16.h>
#include <math.h>

#define NC    128
#define LL    250
#define MM    32
#define NCOL  250000
#define TOT   32000000
#define PERB  8000000
#define PITCH 132

// Scratch
__device__ float g_buf0[32000000];  // u (packed) -> G (glu out, flat) -> u_inter
__device__ float g_buf1[32000000];  // yT -> Lf (lw out, flat)
__device__ float g_kern[NC * LL];
__device__ double g_stats[8];
__device__ float g_mu[4], g_inv[4];
__device__ unsigned g_owAhi[256 * 64];  // ow bf16 hi (u32-packed pairs)
__device__ unsigned g_owAlo[256 * 64];  // ow bf16 lo
__device__ unsigned g_lwWhi[128 * 64];  // lw bf16 hi
__device__ unsigned g_lwWlo[128 * 64];  // lw bf16 lo

// ---------------------------------------------------------------------------
typedef unsigned long long u64;
__device__ __forceinline__ u64 dup2(float x) {
    u64 r; asm("mov.b64 %0,{%1,%1};" : "=l"(r) : "f"(x)); return r;
}
__device__ __forceinline__ u64 pk2(float x, float y) {
    u64 r; asm("mov.b64 %0,{%1,%2};" : "=l"(r) : "f"(x), "f"(y)); return r;
}
__device__ __forceinline__ void fma2(u64& a, u64 b, u64 c) {
    asm("fma.rn.f32x2 %0,%1,%2,%0;" : "+l"(a) : "l"(b), "l"(c));
}
__device__ __forceinline__ void un2(u64 v, float& x, float& y) {
    asm("mov.b64 {%0,%1},%2;" : "=f"(x), "=f"(y) : "l"(v));
}
__device__ __forceinline__ void mma16816(float& c0, float& c1, float& c2, float& c3,
                                         unsigned a0, unsigned a1, unsigned a2, unsigned a3,
                                         unsigned b0, unsigned b1) {
    asm volatile(
        "mma.sync.aligned.m16n8k16.row.col.f32.bf16.bf16.f32 "
        "{%0,%1,%2,%3}, {%4,%5,%6,%7}, {%8,%9}, {%0,%1,%2,%3};"
        : "+f"(c0), "+f"(c1), "+f"(c2), "+f"(c3)
        : "r"(a0), "r"(a1), "r"(a2), "r"(a3), "r"(b0), "r"(b1));
}
__device__ __forceinline__ void ldm4(unsigned& r0, unsigned& r1, unsigned& r2, unsigned& r3,
                                     unsigned a) {
    asm volatile("ldmatrix.sync.aligned.m8n8.x4.shared.b16 {%0,%1,%2,%3}, [%4];"
        : "=r"(r0), "=r"(r1), "=r"(r2), "=r"(r3) : "r"(a));
}
__device__ __forceinline__ unsigned pkbf(__nv_bfloat16 a, __nv_bfloat16 b) {
    unsigned r;
    asm("mov.b32 %0, {%1, %2};" : "=r"(r)
        : "h"(*(unsigned short*)&a), "h"(*(unsigned short*)&b));
    return r;
}
__device__ __forceinline__ unsigned smem_u32p(const void* p) {
    return (unsigned)__cvta_generic_to_shared(p);
}

// ---------------------------------------------------------------------------
__global__ void pack_intra(const float* __restrict__ x) {
    __shared__ float tile[32][33];
    int bh = blockIdx.y;
    int b = bh >> 7, h = bh & 127;
    int tk = blockIdx.x & 7;
    int ts = blockIdx.x >> 3;
    int k = tk * 32 + threadIdx.y;
    int s = ts * 32 + threadIdx.x;
    if (k < 250 && s < 250)
        tile[threadIdx.y][threadIdx.x] = x[(((long)bh * 250 + k) * 250) + s];
    __syncthreads();
    int s2 = ts * 32 + threadIdx.y;
    int k2 = tk * 32 + threadIdx.x;
    if (s2 < 250 && k2 < 250)
        g_buf0[(((long)(b * 250 + s2) * 128 + h) * 250) + k2] = tile[threadIdx.x][threadIdx.y];
}

// ---------------------------------------------------------------------------
__global__ void kern_compute(const float* __restrict__ log_dt,
                             const float* __restrict__ logA_re,
                             const float* __restrict__ A_im,
                             const float* __restrict__ C_re,
                             const float* __restrict__ C_im) {
    __shared__ float sCr[MM], sCi[MM], sar[MM], sai[MM];
    int h = blockIdx.x;
    int t = threadIdx.x;
    if (t < MM) {
        float dt  = expf(log_dt[h]);
        float Are = -expf(logA_re[h * MM + t]);
        float Aim = A_im[h * MM + t];
        float ar = dt * Are, ai = dt * Aim;
        float ea = expf(ar);
        float sb, cb; sincosf(ai, &sb, &cb);
        float er = ea * cb - 1.f, ei = ea * sb;
        float den = Are * Are + Aim * Aim;
        float qr = (er * Are + ei * Aim) / den;
        float qi = (ei * Are - er * Aim) / den;
        float cr = C_re[h * MM + t], ci = C_im[h * MM + t];
        sCr[t] = cr * qr - ci * qi;
        sCi[t] = cr * qi + ci * qr;
        sar[t] = ar; sai[t] = ai;
    }
    __syncthreads();
    if (t < LL) {
        float fl = (float)t;
        float sum = 0.f;
        #pragma unroll
        for (int m = 0; m < MM; ++m) {
            float ea = expf(sar[m] * fl);
            float sb, cb; sincosf(sai[m] * fl, &sb, &cb);
            sum += ea * (sCr[m] * cb - sCi[m] * sb);
        }
        g_kern[h * LL + t] = 2.f * sum;
    }
}

// ---------------------------------------------------------------------------
// Conv as per-h Toeplitz GEMM + D*u + GELU (f32x2 CUDA cores).
__global__ void __launch_bounds__(256, 2)
conv_gemm(const float* __restrict__ D) {
    __shared__ float As[32 * PITCH];
    __shared__ float Bs[32 * PITCH];
    __shared__ float skp[512];
    int tid = threadIdx.x;
    int h = blockIdx.y;
    int rowblk = blockIdx.x >> 1, colblk = blockIdx.x & 1;
    int r0 = rowblk * 128;
    int t0 = colblk * 128;
    int nkt = colblk ? 8 : 4;

    skp[tid] = 0.f;
    skp[256 + tid] = (tid < 250) ? g_kern[h * 250 + tid] : 0.f;
    __syncthreads();

    int tx = tid & 15, ty = tid >> 4;
    u64 acc[8][4];
    #pragma unroll
    for (int i = 0; i < 8; ++i)
        #pragma unroll
        for (int j = 0; j < 4; ++j) acc[i][j] = 0ull;

    for (int kt = 0; kt < nkt; ++kt) {
        int m0 = kt * 32;
        {
            int c4 = (tid & 7) * 4;
            int rb = tid >> 3;
            #pragma unroll
            for (int p = 0; p < 4; ++p) {
                int r = rb + p * 32;
                int bb = r0 + r; if (bb > 999) bb = 999;
                const float* up = g_buf0 + ((long)bb * 128 + h) * 250 + m0 + c4;
                float2 v0 = (m0 + c4     < 250) ? *(const float2*)(up)     : make_float2(0.f, 0.f);
                float2 v1 = (m0 + c4 + 2 < 250) ? *(const float2*)(up + 2) : make_float2(0.f, 0.f);
                As[(c4 + 0) * PITCH + r] = v0.x; As[(c4 + 1) * PITCH + r] = v0.y;
                As[(c4 + 2) * PITCH + r] = v1.x; As[(c4 + 3) * PITCH + r] = v1.y;
            }
        }
        {
            int mm = tid >> 3;
            int ttb = (tid & 7) * 16;
            int base = 256 + t0 - m0 - mm + ttb;
            #pragma unroll
            for (int q = 0; q < 16; ++q)
                Bs[mm * PITCH + ttb + q] = skp[base + q];
        }
        __syncthreads();
        #pragma unroll
        for (int kk = 0; kk < 32; ++kk) {
            float4 a0 = *(const float4*)&As[kk * PITCH + ty * 8];
            float4 a1 = *(const float4*)&As[kk * PITCH + ty * 8 + 4];
            float4 b0 = *(const float4*)&Bs[kk * PITCH + tx * 8];
            float4 b1 = *(const float4*)&Bs[kk * PITCH + tx * 8 + 4];
            u64 ad[8] = {dup2(a0.x), dup2(a0.y), dup2(a0.z), dup2(a0.w),
                         dup2(a1.x), dup2(a1.y), dup2(a1.z), dup2(a1.w)};
            u64 bp4[4] = {pk2(b0.x, b0.y), pk2(b0.z, b0.w),
                          pk2(b1.x, b1.y), pk2(b1.z, b1.w)};
            #pragma unroll
            for (int i = 0; i < 8; ++i)
                #pragma unroll
                for (int j = 0; j < 4; ++j)
                    fma2(acc[i][j], ad[i], bp4[j]);
        }
        __syncthreads();
    }

    float dh = D[h];
    #pragma unroll
    for (int i = 0; i < 8; ++i) {
        int bb = r0 + ty * 8 + i;
        if (bb > 999) continue;
        float c[8];
        #pragma unroll
        for (int j = 0; j < 4; ++j) un2(acc[i][j], c[2 * j], c[2 * j + 1]);
        int tbase = t0 + tx * 8;
        const float* up = g_buf0 + ((long)bb * 128 + h) * 250 + tbase;
        float* yp = g_buf1 + (long)h * NCOL + (long)bb * 250 + tbase;
        #pragma unroll
        for (int j2 = 0; j2 < 4; ++j2) {
            int t = tbase + 2 * j2;
            if (t < 250) {
                float2 uv = *(const float2*)(up + 2 * j2);
                float y0 = c[2 * j2]     + dh * uv.x;
                float y1 = c[2 * j2 + 1] + dh * uv.y;
                float e0 = y0 + 0.044715f * y0 * y0 * y0;
                float e1 = y1 + 0.044715f * y1 * y1 * y1;
                float2 g;
                g.x = 0.5f * y0 * (1.f + tanhf(0.7978845608f * e0));
                g.y = 0.5f * y1 * (1.f + tanhf(0.7978845608f * e1));
                *(float2*)(yp + 2 * j2) = g;
            }
        }
    }
}

// ---------------------------------------------------------------------------
// Pre-convert weights to bf16 hi/lo planes (u32-packed pairs, no duplication).
__global__ void conv_ow_bf16(const float* __restrict__ ow) {
    int idx = blockIdx.x * 256 + threadIdx.x;   // 16384
    int o = idx >> 6, kp = idx & 63;
    float v0 = ow[o * 128 + kp * 2];
    float v1 = ow[o * 128 + kp * 2 + 1];
    __nv_bfloat16 h0 = __float2bfloat16(v0);
    __nv_bfloat16 h1 = __float2bfloat16(v1);
    __nv_bfloat16 l0 = __float2bfloat16(v0 - __bfloat162float(h0));
    __nv_bfloat16 l1 = __float2bfloat16(v1 - __bfloat162float(h1));
    g_owAhi[o * 64 + kp] = pkbf(h0, h1);
    g_owAlo[o * 64 + kp] = pkbf(l0, l1);
}

__global__ void conv_lw_bf16(const float* __restrict__ W) {
    int idx = blockIdx.x * 256 + threadIdx.x;   // 8192
    int c = idx >> 6, kp = idx & 63;
    float v0 = W[c * 128 + kp * 2];
    float v1 = W[c * 128 + kp * 2 + 1];
    __nv_bfloat16 h0 = __float2bfloat16(v0);
    __nv_bfloat16 h1 = __float2bfloat16(v1);
    __nv_bfloat16 l0 = __float2bfloat16(v0 - __bfloat162float(h0));
    __nv_bfloat16 l1 = __float2bfloat16(v1 - __bfloat162float(h1));
    g_lwWhi[c * 64 + kp] = pkbf(h0, h1);
    g_lwWlo[c * 64 + kp] = pkbf(l0, l1);
}

// ---------------------------------------------------------------------------
// ow GEMM + GLU: fully smem-resident operands, sync-free mainloop.
// m-tiles per warp: rows {mw*32, mw*32+16, 128+mw*32, 144+mw*32}
// -> thread-local z1/z2 GLU pairs (no stash).
// Dyn smem: Ahi [256][68] u32 @0 (69632) | Alo @69632 (69632)
//           | Bs16 bf16[64][392] @139264 (50176) | sbias @189440 (1024)
__global__ void __launch_bounds__(256)
gemm_ow_mma(const float* __restrict__ bias) {
    extern __shared__ char dsm[];
    unsigned* Ahi = (unsigned*)dsm;
    __nv_bfloat16* Bs16 = (__nv_bfloat16*)(dsm + 139264);
    float* sbias = (float*)(dsm + 189440);

    int tid = threadIdx.x;
    int w = tid >> 5, lane = tid & 31;
    int g = lane >> 2, tg = lane & 3;
    int mw = w >> 1, nw = w & 1;
    long n0 = (long)blockIdx.x * 64;

    sbias[tid] = bias[tid];

    // Copy weight hi/lo planes into padded smem (once)
    #pragma unroll
    for (int p = 0; p < 16; ++p) {
        int i = tid + p * 256;            // 4096 uint4
        int o = i >> 4, q = i & 15;
        uint4 vh = ((const uint4*)g_owAhi)[o * 16 + q];
        uint4 vl = ((const uint4*)g_owAlo)[o * 16 + q];
        *(uint4*)&Ahi[o * 68 + q * 4] = vh;
        *(uint4*)(dsm + 69632 + (o * 68 + q * 4) * 4) = vl;
    }

    // Build B3 from yT
    for (int i = tid; i < 128 * 64; i += 256) {
        int hk = i >> 6, c = i & 63;
        long col = n0 + c; if (col >= NCOL) col = NCOL - 1;
        float v = g_buf1[(long)hk * NCOL + col];
        __nv_bfloat16 hi = __float2bfloat16(v);
        __nv_bfloat16 lo = __float2bfloat16(v - __bfloat162float(hi));
        __nv_bfloat16* bp = Bs16 + c * 392;
        bp[hk] = hi; bp[hk + 128] = lo; bp[hk + 256] = hi;
    }
    __syncthreads();

    // Per-lane ldmatrix bases
    unsigned aAddr = smem_u32p(Ahi)
        + (((lane & 7) + ((lane >> 3) & 1) * 8 + mw * 32) * 68 + (lane >> 4) * 4) * 4;
    unsigned bAddr = smem_u32p(Bs16)
        + ((lane & 7) + (lane >> 4) * 8 + nw * 32) * 784 + ((lane >> 3) & 1) * 16;

    float acc[4][4][4];
    #pragma unroll
    for (int i = 0; i < 4; ++i)
        #pragma unroll
        for (int j = 0; j < 4; ++j)
            #pragma unroll
            for (int q = 0; q < 4; ++q) acc[i][j][q] = 0.f;

    const unsigned tOff[4] = {0u, 16u * 272u, 128u * 272u, 144u * 272u};

    #pragma unroll
    for (int ks = 0; ks < 24; ++ks) {
        unsigned aoff = (ks < 16) ? (unsigned)(ks & 7) * 32u
                                  : 69632u + (unsigned)(ks - 16) * 32u;
        unsigned bf0[4], bf1[4];
        #pragma unroll
        for (int jp = 0; jp < 2; ++jp)
            ldm4(bf0[2 * jp], bf1[2 * jp], bf0[2 * jp + 1], bf1[2 * jp + 1],
                 bAddr + jp * 16 * 784 + ks * 32);
        #pragma unroll
        for (int i = 0; i < 4; ++i) {
            unsigned a0, a1, a2, a3;
            ldm4(a0, a1, a2, a3, aAddr + tOff[i] + aoff);
            #pragma unroll
            for (int j = 0; j < 4; ++j)
                mma16816(acc[i][j][0], acc[i][j][1], acc[i][j][2], acc[i][j][3],
                         a0, a1, a2, a3, bf0[j], bf1[j]);
        }
    }

    // GLU epilogue: tiles i (z1) pair with i+2 (z2), all thread-local.
    #pragma unroll
    for (int i = 0; i < 2; ++i) {
        int oa = mw * 32 + i * 16 + g;
        int ob = oa + 8;
        float b1a = sbias[oa],       b1b = sbias[ob];
        float b2a = sbias[128 + oa], b2b = sbias[128 + ob];
        #pragma unroll
        for (int j = 0; j < 4; ++j) {
            int cl = nw * 32 + j * 8 + tg * 2;
            long col = n0 + cl;
            if (col < NCOL) {
                int bb = (int)(col / 250);
                int l  = (int)(col - (long)bb * 250);
                float z1a = acc[i][j][0] + b1a;
                float z1b = acc[i][j][1] + b1a;
                float z2a = acc[i + 2][j][0] + b2a;
                float z2b = acc[i + 2][j][1] + b2a;
                float2 gv;
                gv.x = z1a / (1.f + expf(-z2a));
                gv.y = z1b / (1.f + expf(-z2b));
                *(float2*)&g_buf0[((long)bb * 128 + oa) * 250 + l] = gv;
                float z3a = acc[i][j][2] + b1b;
                float z3b = acc[i][j][3] + b1b;
                float z4a = acc[i + 2][j][2] + b2b;
                float z4b = acc[i + 2][j][3] + b2b;
                float2 gw;
                gw.x = z3a / (1.f + expf(-z4a));
                gw.y = z3b / (1.f + expf(-z4b));
                *(float2*)&g_buf0[((long)bb * 128 + ob) * 250 + l] = gw;
            }
        }
    }
}

// ---------------------------------------------------------------------------
// lw GEMM + stats: G and W hi/lo planes all smem-resident, sync-free mainloop.
// Dyn smem: Ghi [128][68] u32 @0 (34816) | Glo @34816 | Whi @69632 | Wlo @104448
//           | sbias @139264 (512) | red @139776 (128)
__global__ void __launch_bounds__(256)
gemm_lw_mma(const float* __restrict__ bias) {
    extern __shared__ char dsm[];
    unsigned* Ghi = (unsigned*)dsm;
    unsigned* Glo = (unsigned*)(dsm + 34816);
    unsigned* Whi = (unsigned*)(dsm + 69632);
    unsigned* Wlo = (unsigned*)(dsm + 104448);
    float* sbias = (float*)(dsm + 139264);
    float* red = (float*)(dsm + 139776);     // [8][4]

    int tid = threadIdx.x;
    int w = tid >> 5, lane = tid & 31;
    int g = lane >> 2, tg = lane & 3;
    int mw = w >> 1, nw = w & 1;
    long r0 = (long)blockIdx.x * 128;

    if (tid < 128) sbias[tid] = bias[tid];

    // Copy W hi/lo planes
    #pragma unroll
    for (int p = 0; p < 8; ++p) {
        int i = tid + p * 256;            // 2048 uint4
        int c = i >> 4, q = i & 15;
        uint4 vh = ((const uint4*)g_lwWhi)[c * 16 + q];
        uint4 vl = ((const uint4*)g_lwWlo)[c * 16 + q];
        *(uint4*)&Whi[c * 68 + q * 4] = vh;
        *(uint4*)&Wlo[c * 68 + q * 4] = vl;
    }

    // Convert G block once
    #pragma unroll
    for (int p = 0; p < 32; ++p) {
        int i = tid + p * 256;
        int r = i >> 6, kk = i & 63;
        long row = r0 + r; if (row >= NCOL) row = NCOL - 1;
        float2 v = *(const float2*)&g_buf0[row * 128 + kk * 2];
        __nv_bfloat16 h0 = __float2bfloat16(v.x);
        __nv_bfloat16 h1 = __float2bfloat16(v.y);
        __nv_bfloat16 l0 = __float2bfloat16(v.x - __bfloat162float(h0));
        __nv_bfloat16 l1 = __float2bfloat16(v.y - __bfloat162float(h1));
        Ghi[r * 68 + kk] = pkbf(h0, h1);
        Glo[r * 68 + kk] = pkbf(l0, l1);
    }
    __syncthreads();

    unsigned aAddr = smem_u32p(Ghi)
        + (((lane & 7) + ((lane >> 3) & 1) * 8 + mw * 32) * 68 + (lane >> 4) * 4) * 4;
    unsigned bAddr = smem_u32p(Whi)
        + ((lane & 7) + (lane >> 4) * 8 + nw * 64) * 272 + ((lane >> 3) & 1) * 16;

    float acc[2][8][4];
    #pragma unroll
    for (int i = 0; i < 2; ++i)
        #pragma unroll
        for (int j = 0; j < 8; ++j)
            #pragma unroll
            for (int q = 0; q < 4; ++q) acc[i][j][q] = 0.f;

    #pragma unroll
    for (int ks = 0; ks < 24; ++ks) {
        // A: ks<16 -> Ghi(ks&7), else Glo(ks-16)
        unsigned aoff = (ks < 16) ? (unsigned)(ks & 7) * 32u
                                  : 34816u + (unsigned)(ks - 16) * 32u;
        // B: ks<8 -> Whi(ks); 8..15 -> Wlo(ks-8); 16..23 -> Whi(ks-16)
        unsigned boff = (ks < 8) ? (unsigned)ks * 32u
                      : (ks < 16) ? 34816u + (unsigned)(ks - 8) * 32u
                                  : (unsigned)(ks - 16) * 32u;
        unsigned bf0[8], bf1[8];
        #pragma unroll
        for (int jp = 0; jp < 4; ++jp)
            ldm4(bf0[2 * jp], bf1[2 * jp], bf0[2 * jp + 1], bf1[2 * jp + 1],
                 bAddr + jp * 16 * 272 + boff);
        #pragma unroll
        for (int i = 0; i < 2; ++i) {
            unsigned a0, a1, a2, a3;
            ldm4(a0, a1, a2, a3, aAddr + aoff + i * 16 * 272);
            #pragma unroll
            for (int j = 0; j < 8; ++j)
                mma16816(acc[i][j][0], acc[i][j][1], acc[i][j][2], acc[i][j][3],
                         a0, a1, a2, a3, bf0[j], bf1[j]);
        }
    }

    // Epilogue: bias, store, stats
    int b0idx = (int)(r0 / 62500);
    float s0 = 0.f, q0 = 0.f, s1 = 0.f, q1 = 0.f;
    #pragma unroll
    for (int i = 0; i < 2; ++i) {
        long ra = r0 + mw * 32 + i * 16 + g;
        long rb = ra + 8;
        #pragma unroll
        for (int j = 0; j < 8; ++j) {
            int c = nw * 64 + j * 8 + tg * 2;
            float bv0 = sbias[c], bv1 = sbias[c + 1];
            if (ra < NCOL) {
                float v0 = acc[i][j][0] + bv0;
                float v1 = acc[i][j][1] + bv1;
                *(float2*)&g_buf1[ra * 128 + c] = make_float2(v0, v1);
                float rs = v0 + v1, rq = v0 * v0 + v1 * v1;
                if ((int)(ra / 62500) == b0idx) { s0 += rs; q0 += rq; }
                else                            { s1 += rs; q1 += rq; }
            }
            if (rb < NCOL) {
                float v2 = acc[i][j][2] + bv0;
                float v3 = acc[i][j][3] + bv1;
                *(float2*)&g_buf1[rb * 128 + c] = make_float2(v2, v3);
                float rs = v2 + v3, rq = v2 * v2 + v3 * v3;
                if ((int)(rb / 62500) == b0idx) { s0 += rs; q0 += rq; }
                else                            { s1 += rs; q1 += rq; }
            }
        }
    }
    #pragma unroll
    for (int off = 16; off; off >>= 1) {
        s0 += __shfl_down_sync(0xffffffffu, s0, off);
        q0 += __shfl_down_sync(0xffffffffu, q0, off);
        s1 += __shfl_down_sync(0xffffffffu, s1, off);
        q1 += __shfl_down_sync(0xffffffffu, q1, off);
    }
    if (lane == 0) { red[w * 4 + 0] = s0; red[w * 4 + 1] = q0; red[w * 4 + 2] = s1; red[w * 4 + 3] = q1; }
    __syncthreads();
    if (tid == 0) {
        float ts0 = 0.f, tq0 = 0.f, ts1 = 0.f, tq1 = 0.f;
        #pragma unroll
        for (int j = 0; j < 8; ++j) {
            ts0 += red[j * 4 + 0]; tq0 += red[j * 4 + 1];
            ts1 += red[j * 4 + 2]; tq1 += red[j * 4 + 3];
        }
        atomicAdd(&g_stats[2 * b0idx],     (double)ts0);
        atomicAdd(&g_stats[2 * b0idx + 1], (double)tq0);
        if (b0idx < 3) {
            atomicAdd(&g_stats[2 * b0idx + 2], (double)ts1);
            atomicAdd(&g_stats[2 * b0idx + 3], (double)tq1);
        }
    }
}

// ---------------------------------------------------------------------------
__global__ void zero_stats() {
    if (threadIdx.x < 8) g_stats[threadIdx.x] = 0.0;
}

__global__ void finalize_stats() {
    int b = threadIdx.x;
    if (b < 4) {
        double mu  = g_stats[2 * b] / (double)PERB;
        double var = g_stats[2 * b + 1] / (double)PERB - mu * mu;
        g_mu[b]  = (float)mu;
        g_inv[b] = (float)(1.0 / sqrt(var + 1e-8));
    }
}

__global__ void trans_norm_intra(const float* __restrict__ gg, const float* __restrict__ gb,
                                 const float* __restrict__ x, float* __restrict__ out) {
    __shared__ float tile[32][33];
    int bn = blockIdx.y;
    int b = bn >> 7, n = bn & 127;
    int tk = blockIdx.x & 7, ts = blockIdx.x >> 3;
    int s = ts * 32 + threadIdx.y;
    int k = tk * 32 + threadIdx.x;
    if (s < 250 && k < 250)
        tile[threadIdx.y][threadIdx.x] =
            g_buf1[((long)(b * 250 + s)) * 32000 + n * 250 + k];
    __syncthreads();
    int k2 = tk * 32 + threadIdx.y;
    int s2 = ts * 32 + threadIdx.x;
    if (k2 < 250 && s2 < 250) {
        float mu = g_mu[b], inv = g_inv[b];
        long oi = (((long)(b * 128 + n)) * 250 + k2) * 250 + s2;
        float val = (tile[threadIdx.x][threadIdx.y] - mu) * inv * gg[n] + gb[n] + x[oi];
        out[oi] = val;
        g_buf0[(((long)(b * 250 + k2)) * 128 + n) * 250 + s2] = val;
    }
}

__global__ void norm_final(const float* __restrict__ gg, const float* __restrict__ gb,
                           float* __restrict__ out) {
    int i = blockIdx.x * 256 + threadIdx.x;
    int s = i % 250;
    int t = i / 250;
    int k = t % 250; t /= 250;
    int n = t & 127;
    int b = t >> 7;
    float mu = g_mu[b], inv = g_inv[b];
    float v = g_buf1[((long)(b * 250 + k)) * 32000 + n * 250 + s];
    out[i] = (v - mu) * inv * gg[n] + gb[n] + out[i];
}

// ---------------------------------------------------------------------------
extern "C" void kernel_launch(void* const* d_in, const int* in_sizes, int n_in,
                              void* d_out, int out_size) {
    const float* x = (const float*)d_in[0];
    const float* ip[12];
    const float* pp[12];
    for (int j = 0; j < 12; ++j) ip[j] = (const float*)d_in[1 + j];
    for (int j = 0; j < 12; ++j) pp[j] = (const float*)d_in[13 + j];
    float* out = (float*)d_out;

    const int EB = TOT / 256;
    const int SMEM_OW = 190464;
    const int SMEM_LW = 139904;
    cudaFuncSetAttribute(gemm_ow_mma, cudaFuncAttributeMaxDynamicSharedMemorySize, SMEM_OW);
    cudaFuncSetAttribute(gemm_lw_mma, cudaFuncAttributeMaxDynamicSharedMemorySize, SMEM_LW);
    const int GOW = (NCOL + 63) / 64;   // 3907

    // ---- intra path ----
    pack_intra<<<dim3(64, 512), dim3(32, 32)>>>(x);
    kern_compute<<<NC, 256>>>(ip[0], ip[1], ip[2], ip[3], ip[4]);
    conv_gemm<<<dim3(16, 128), 256>>>(ip[5]);
    conv_ow_bf16<<<64, 256>>>(ip[6]);
    conv_lw_bf16<<<32, 256>>>(ip[8]);
    gemm_ow_mma<<<GOW, 256, SMEM_OW>>>(ip[7]);
    zero_stats<<<1, 32>>>();
    gemm_lw_mma<<<1954, 256, SMEM_LW>>>(ip[9]);
    finalize_stats<<<1, 32>>>();
    trans_norm_intra<<<dim3(64, 512), dim3(32, 32)>>>(ip[10], ip[11], x, out);

    // ---- inter path ----
    kern_compute<<<NC, 256>>>(pp[0], pp[1], pp[2], pp[3], pp[4]);
    conv_gemm<<<dim3(16, 128), 256>>>(pp[5]);
    conv_ow_bf16<<<64, 256>>>(pp[6]);
    conv_lw_bf16<<<32, 256>>>(pp[8]);
    gemm_ow_mma<<<GOW, 256, SMEM_OW>>>(pp[7]);
    zero_stats<<<1, 32>>>();
    gemm_lw_mma<<<1954, 256, SMEM_LW>>>(pp[9]);
    finalize_stats<<<1, 32>>>();
    norm_final<<<EB, 256>>>(pp[10], pp[11], out);
}